// round 9
// baseline (speedup 1.0000x reference)
#include <cuda_runtime.h>
#include <math.h>

// Hausdorff, D=H=W=20, V=8000, batch 2. Exact integer squared-EDT.
// ONE kernel, 20 blocks: block = z-plane z0, computing ALL 4 transforms
// (2 samples x 2 directions). Each thread (x,y) loads its z-row of both
// masks of both samples as 20-bit words -> z-pass O(1), s/o/oo flags free.
// y/x passes in SMEM (4 planes, 2 syncs). anyA is block-local (full masks
// visible in every block). Tail: <=4 atomicMax + one 20-arrival counter.

#define INF_S 32000   // max legit squared distance = 3*19^2 = 1083
#define PAD   8

__device__ unsigned g_gmax[4 * PAD];   // per-transform max d2+1 (0 = none); zero-init
__device__ unsigned g_done = 0;        // arrival counter

__device__ __forceinline__ unsigned rowbits_of(const float* p)
{
    const float4* rp = (const float4*)p;
    unsigned bits = 0;
    #pragma unroll
    for (int q = 0; q < 5; q++) {
        float4 v = rp[q];
        // jnp.round == round-half-even == rintf
        bits |= (rintf(v.x) != 0.0f ? 1u : 0u) << (q * 4 + 0);
        bits |= (rintf(v.y) != 0.0f ? 1u : 0u) << (q * 4 + 1);
        bits |= (rintf(v.z) != 0.0f ? 1u : 0u) << (q * 4 + 2);
        bits |= (rintf(v.w) != 0.0f ? 1u : 0u) << (q * 4 + 3);
    }
    return bits;
}

__device__ __forceinline__ int zdist2(unsigned bits, int z0)
{
    int dist = 100;
    unsigned lo = bits & ((2u << z0) - 1u);
    if (lo) dist = z0 - (31 - __clz(lo));
    unsigned hi = bits >> z0;
    if (hi) dist = min(dist, __ffs(hi) - 1);
    return (dist <= 19) ? dist * dist : INF_S;
}

__global__ void __launch_bounds__(416, 1)
haus_plane4(const float* __restrict__ predict,
            const float* __restrict__ targetp,
            float* __restrict__ out)
{
    __shared__ int F1[4][400];
    __shared__ int F2[4][400];
    __shared__ int sred[4];
    __shared__ int sany[2];

    const int z0  = blockIdx.x;          // 0..19
    const int tid = threadIdx.x;

    if (tid < 4) sred[tid] = 0;
    if (tid < 2) sany[tid] = 0;

    int x = 0, y = 0;
    unsigned bA0 = 0, bB0 = 0, bA1 = 0, bB1 = 0;
    int oo[4] = {0, 0, 0, 0};
    if (tid < 400) {
        x = tid / 20; y = tid - x * 20;
        const int off = tid * 20;
        bA0 = rowbits_of(predict + off);          // sample 0, mask A
        bB0 = rowbits_of(targetp + off);          // sample 0, mask B
        bA1 = rowbits_of(predict + 8000 + off);   // sample 1, mask A
        bB1 = rowbits_of(targetp + 8000 + off);   // sample 1, mask B

        // z-pass for all 4 transforms (t = n*2+m; set = m? B : A)
        F1[0][tid] = zdist2(bA0, z0);
        F1[1][tid] = zdist2(bB0, z0);
        F1[2][tid] = zdist2(bA1, z0);
        F1[3][tid] = zdist2(bB1, z0);

        int a0 = (bA0 >> z0) & 1, b0 = (bB0 >> z0) & 1;
        int a1 = (bA1 >> z0) & 1, b1 = (bB1 >> z0) & 1;
        oo[0] = b0 & (a0 ^ 1);   // t=0 set=A: B-only points
        oo[1] = a0 & (b0 ^ 1);   // t=1 set=B: A-only points
        oo[2] = b1 & (a1 ^ 1);
        oo[3] = a1 & (b1 ^ 1);
    }
    // anyA per sample — full mask visible in-block via row bits
    int any0 = __any_sync(0xffffffffu, bA0 != 0);
    int any1 = __any_sync(0xffffffffu, bA1 != 0);
    if ((tid & 31) == 0) {                       // benign races: writers store 1
        if (any0) sany[0] = 1;
        if (any1) sany[1] = 1;
    }
    __syncthreads();

    // ---- y-pass: F2[t](x,y) = min_yp F1[t](x,yp) + (y-yp)^2 ----
    if (tid < 400) {
        #pragma unroll
        for (int t = 0; t < 4; t++) {
            int c[20];
            const int base = x * 20;
            #pragma unroll
            for (int yp = 0; yp < 20; yp++) {
                int dy = y - yp;
                c[yp] = F1[t][base + yp] + dy * dy;
            }
            #pragma unroll
            for (int st = 1; st < 20; st <<= 1)
                #pragma unroll
                for (int i = 0; i + st < 20; i += (st << 1)) c[i] = min(c[i], c[i + st]);
            F2[t][tid] = c[0];
        }
    }
    __syncthreads();

    // ---- x-pass + classification, all 4 transforms ----
    int enc[4] = {0, 0, 0, 0};                   // best+1; 0 = none
    if (tid < 400) {
        #pragma unroll
        for (int t = 0; t < 4; t++) {
            int c[20];
            #pragma unroll
            for (int xp = 0; xp < 20; xp++) {
                int dx = x - xp;
                c[xp] = F2[t][xp * 20 + y] + dx * dx;
            }
            #pragma unroll
            for (int st = 1; st < 20; st <<= 1)
                #pragma unroll
                for (int i = 0; i + st < 20; i += (st << 1)) c[i] = min(c[i], c[i + st]);
            if (oo[t]) enc[t] = c[0] + 1;
        }
    }
    #pragma unroll
    for (int t = 0; t < 4; t++) {
        int e = __reduce_max_sync(0xffffffffu, enc[t]);
        if ((tid & 31) == 0 && e) atomicMax(&sred[t], e);
    }
    __syncthreads();

    // ---- tail: <=4 global atomicMax (overlapped) + one 20-arrival counter ----
    if (tid == 0) {
        #pragma unroll
        for (int t = 0; t < 4; t++)
            if (sred[t]) atomicMax(&g_gmax[t * PAD], (unsigned)sred[t]);
        __threadfence();
        unsigned done = atomicAdd(&g_done, 1);
        if (done == 19) {
            __threadfence();
            volatile unsigned* vmax = (volatile unsigned*)g_gmax;
            float sum = 0.0f;
            #pragma unroll
            for (int nn = 0; nn < 2; nn++) {
                int a2   = (int)vmax[(nn * 2 + 1) * PAD] - 1;  // A-only -> B (set=B)
                int b2   = (int)vmax[(nn * 2 + 0) * PAD] - 1;  // B-only -> A (set=A)
                int anyA = sany[nn];                           // block-local, exact
                float dA = 0.0f;
                if (a2 >= 0) dA = (a2 > 1083) ? 1e9f : sqrtf((float)a2) * 0.05f;
                float dB = 0.0f;
                if (b2 >= 0) dB = anyA ? ((b2 > 1083) ? 1e9f : sqrtf((float)b2) * 0.05f)
                                       : 999.0f;
                sum += fmaxf(dA, dB);
                vmax[(nn * 2 + 0) * PAD] = 0;
                vmax[(nn * 2 + 1) * PAD] = 0;
            }
            out[0] = sum * 0.5f;
            *(volatile unsigned*)&g_done = 0;     // restore static-init state
        }
    }
}

extern "C" void kernel_launch(void* const* d_in, const int* in_sizes, int n_in,
                              void* d_out, int out_size)
{
    const float* predict = (const float*)d_in[0];
    const float* targetp = (const float*)d_in[1];
    haus_plane4<<<20, 416>>>(predict, targetp, (float*)d_out);
}

// round 10
// speedup vs baseline: 1.1364x; 1.1364x over previous
#include <cuda_runtime.h>
#include <math.h>

// Hausdorff, D=H=W=20, V=8000, batch 2. Exact integer squared-EDT.
// ONE kernel, 80 blocks: block = (transform t, z-plane z0). COALESCED volume
// loads (each warp 1 line/access, MLP=20) + smem atomicOr builds per-(x,y)
// 20-bit z-occupancy; z-pass O(1) via clz/ffs; y/x passes tree-min in SMEM.
// Tail: per-block atomicMax + 80-arrival counter; last block finalizes+resets.

#define INF_S 32000   // max legit squared distance = 3*19^2 = 1083
#define PAD   8

__device__ unsigned g_gmax[4 * PAD];   // per-transform max d2+1 (0 = none); zero-init
__device__ unsigned g_any[2 * PAD];    // any(mask A) per sample; zero-init
__device__ unsigned g_done = 0;

__global__ void __launch_bounds__(416, 1)
haus_plane(const float* __restrict__ predict,
           const float* __restrict__ targetp,
           float* __restrict__ out)
{
    __shared__ unsigned rowbits[400];  // z-occupancy bits per (x,y) row
    __shared__ int F1[400];
    __shared__ int F2[400];
    __shared__ int sred;
    __shared__ int sany;

    const int b  = blockIdx.x;         // t*20 + z0
    const int t  = b / 20, z0 = b - t * 20;
    const int n  = t >> 1,  m  = t & 1;
    const float* setSrc = (m ? targetp : predict) + n * 8000;
    const float* othSrc = (m ? predict : targetp) + n * 8000;
    const int tid = threadIdx.x;

    if (tid < 400) rowbits[tid] = 0;
    if (tid == 0) { sred = 0; sany = 0; }

    // early "other" load at own cell (strided; single issue, latency hidden)
    float ov = 0.0f;
    if (tid < 400) ov = othSrc[tid * 20 + z0];
    __syncthreads();

    // ---- coalesced volume sweep -> rowbits via smem atomicOr ----
    int anybit = 0;
    #pragma unroll
    for (int k = 0; k < 20; k++) {
        int i = tid + k * 416;
        if (i < 8000) {
            // jnp.round == round-half-even == rintf
            if (rintf(setSrc[i]) != 0.0f) {
                anybit = 1;
                atomicOr(&rowbits[i / 20], 1u << (i % 20));
            }
        }
    }
    int anyW = __any_sync(0xffffffffu, anybit);
    if ((tid & 31) == 0 && anyW) sany = 1;       // benign race
    __syncthreads();

    int x = 0, y = 0, oo = 0;
    if (tid < 400) {
        x = tid / 20; y = tid - x * 20;
        unsigned bits = rowbits[tid];
        // z-pass at fixed z0: nearest set bit, O(1)
        int dist = 100;
        unsigned lo = bits & ((2u << z0) - 1u);
        if (lo) dist = z0 - (31 - __clz(lo));
        unsigned hi = bits >> z0;
        if (hi) dist = min(dist, __ffs(hi) - 1);
        F1[tid] = (dist <= 19) ? dist * dist : INF_S;

        int s = (bits >> z0) & 1;
        oo = (rintf(ov) != 0.0f) & (s ^ 1);      // "other-only" point
    }
    __syncthreads();

    // ---- y-pass: F2(x,y) = min_yp F1(x,yp) + (y-yp)^2 (tree-min) ----
    if (tid < 400) {
        int c[20];
        const int base = x * 20;
        #pragma unroll
        for (int yp = 0; yp < 20; yp++) {
            int dy = y - yp;
            c[yp] = F1[base + yp] + dy * dy;
        }
        #pragma unroll
        for (int st = 1; st < 20; st <<= 1)
            #pragma unroll
            for (int i = 0; i + st < 20; i += (st << 1)) c[i] = min(c[i], c[i + st]);
        F2[tid] = c[0];
    }
    __syncthreads();

    // ---- x-pass + classification ----
    int enc = 0;                                  // best+1; 0 = none
    if (tid < 400) {
        int c[20];
        #pragma unroll
        for (int xp = 0; xp < 20; xp++) {
            int dx = x - xp;
            c[xp] = F2[xp * 20 + y] + dx * dx;
        }
        #pragma unroll
        for (int st = 1; st < 20; st <<= 1)
            #pragma unroll
            for (int i = 0; i + st < 20; i += (st << 1)) c[i] = min(c[i], c[i + st]);
        if (oo) enc = c[0] + 1;
    }
    enc = __reduce_max_sync(0xffffffffu, enc);
    if ((tid & 31) == 0 && enc) atomicMax(&sred, enc);
    __syncthreads();

    // ---- tail ----
    if (tid == 0) {
        if (sred) atomicMax(&g_gmax[t * PAD], (unsigned)sred);
        if (m == 0 && z0 == 0)                    // single writer per sample
            *(volatile unsigned*)&g_any[n * PAD] = (unsigned)sany;
        __threadfence();
        unsigned done = atomicAdd(&g_done, 1);
        if (done == 79) {
            __threadfence();
            volatile unsigned* vmax = (volatile unsigned*)g_gmax;
            volatile unsigned* vany = (volatile unsigned*)g_any;
            float sum = 0.0f;
            #pragma unroll
            for (int nn = 0; nn < 2; nn++) {
                int a2   = (int)vmax[(nn * 2 + 1) * PAD] - 1;  // A-only -> B (set=B)
                int b2   = (int)vmax[(nn * 2 + 0) * PAD] - 1;  // B-only -> A (set=A)
                int anyA = (int)vany[nn * PAD];
                float dA = 0.0f;
                if (a2 >= 0) dA = (a2 > 1083) ? 1e9f : sqrtf((float)a2) * 0.05f;
                float dB = 0.0f;
                if (b2 >= 0) dB = anyA ? ((b2 > 1083) ? 1e9f : sqrtf((float)b2) * 0.05f)
                                       : 999.0f;
                sum += fmaxf(dA, dB);
                vmax[(nn * 2 + 0) * PAD] = 0;
                vmax[(nn * 2 + 1) * PAD] = 0;
                vany[nn * PAD] = 0;
            }
            out[0] = sum * 0.5f;
            *(volatile unsigned*)&g_done = 0;     // restore static-init state
        }
    }
}

extern "C" void kernel_launch(void* const* d_in, const int* in_sizes, int n_in,
                              void* d_out, int out_size)
{
    const float* predict = (const float*)d_in[0];
    const float* targetp = (const float*)d_in[1];
    haus_plane<<<80, 416>>>(predict, targetp, (float*)d_out);
}